// round 3
// baseline (speedup 1.0000x reference)
#include <cuda_runtime.h>
#include <math.h>

// ---------------------------------------------------------------------------
// AGNN: features[100000,128] f32, src/dst[1.6M] int32, w1[32,128], b1[32],
//       betas[2], w2[64,32], b2[64]  ->  out[100000,64] f32 (log_softmax)
//
// Pipeline:
//   K1  gemm1+relu+rownorm  : h1 = relu(F @ w1^T + b1), rinv = 1/max(||h1||,eps)
//   per layer L in {0,1}:
//     zero(denom + agg)  (one kernel)
//     K2  edge: e = beta*rinv[s]*rinv[d]*dot(h[s],h[d]); ex=exp(e);
//               denom[d] += ex            (max-subtraction skipped: |e|<=|beta|)
//     K3  scatter: alpha = ex/max(denom[d],eps); agg[d] += alpha*h[s] (RED.v4)
//     K4  relu+rownorm on agg (layer0 only; layer1 relu fused into K5)
//   K5  head: out = log_softmax(relu(h2) @ w2^T + b2)
// ---------------------------------------------------------------------------

#define NN 100000
#define NE 1600000
#define EPSF 1e-12f

__device__ __align__(128) float g_bufA[NN * 32];
__device__ __align__(128) float g_bufB[NN * 32];
__device__ __align__(128) float g_rinv[NN];
__device__ __align__(128) float g_ex[NE];
__device__ __align__(128) float g_denom[NN];

// ---------------------------------------------------------------------------
// Zero agg (n*32 floats) and denom (n floats) in one kernel.
__global__ void k_zero_layer(float4* __restrict__ agg, float4* __restrict__ denom,
                             int n_agg4, int n_den4) {
    int i = blockIdx.x * blockDim.x + threadIdx.x;
    if (i < n_agg4) agg[i] = make_float4(0.f, 0.f, 0.f, 0.f);
    if (i < n_den4) denom[i] = make_float4(0.f, 0.f, 0.f, 0.f);
}

// ---------------------------------------------------------------------------
// GEMM1: thread-per-node, w1 transposed into smem, 32 accumulators.
__global__ __launch_bounds__(256) void k_gemm1(
    const float* __restrict__ feat, const float* __restrict__ w1,
    const float* __restrict__ b1, float* __restrict__ h,
    float* __restrict__ rinv, int n)
{
    __shared__ float w1t[128 * 32];   // [k][j]
    __shared__ float b1s[32];
    for (int i = threadIdx.x; i < 4096; i += 256) {
        int j = i >> 7, k = i & 127;
        w1t[k * 32 + j] = w1[i];
    }
    if (threadIdx.x < 32) b1s[threadIdx.x] = b1[threadIdx.x];
    __syncthreads();

    int node = blockIdx.x * 256 + threadIdx.x;
    if (node >= n) return;

    float acc[32];
    #pragma unroll
    for (int j = 0; j < 32; j++) acc[j] = b1s[j];

    const float4* f4 = reinterpret_cast<const float4*>(feat + (size_t)node * 128);
    #pragma unroll 4
    for (int k4 = 0; k4 < 32; k4++) {
        float4 f = f4[k4];
        float fv[4] = {f.x, f.y, f.z, f.w};
        #pragma unroll
        for (int c = 0; c < 4; c++) {
            const float4* w4 = reinterpret_cast<const float4*>(&w1t[(k4 * 4 + c) * 32]);
            #pragma unroll
            for (int j4 = 0; j4 < 8; j4++) {
                float4 w = w4[j4];
                acc[j4 * 4 + 0] += fv[c] * w.x;
                acc[j4 * 4 + 1] += fv[c] * w.y;
                acc[j4 * 4 + 2] += fv[c] * w.z;
                acc[j4 * 4 + 3] += fv[c] * w.w;
            }
        }
    }

    float ss = 0.f;
    #pragma unroll
    for (int j = 0; j < 32; j++) {
        float v = fmaxf(acc[j], 0.f);
        acc[j] = v;
        ss += v * v;
    }
    rinv[node] = 1.0f / fmaxf(sqrtf(ss), EPSF);

    float4* o4 = reinterpret_cast<float4*>(h + (size_t)node * 32);
    #pragma unroll
    for (int j4 = 0; j4 < 8; j4++)
        o4[j4] = make_float4(acc[j4 * 4], acc[j4 * 4 + 1], acc[j4 * 4 + 2], acc[j4 * 4 + 3]);
}

// ---------------------------------------------------------------------------
// Edge pass 1: e = beta * rinv[s]*rinv[d] * dot(h[s],h[d]); ex=exp(e); denom[d]+=ex
__global__ __launch_bounds__(256) void k_edge(
    const int* __restrict__ src, const int* __restrict__ dst,
    const float* __restrict__ h, const float* __restrict__ rinv,
    const float* __restrict__ betas, int layer,
    float* __restrict__ ex, float* __restrict__ denom, int ne)
{
    int e = blockIdx.x * 256 + threadIdx.x;
    if (e >= ne) return;
    int s = src[e];
    int d = dst[e];

    const float4* hs = reinterpret_cast<const float4*>(h + (size_t)s * 32);
    const float4* hd = reinterpret_cast<const float4*>(h + (size_t)d * 32);
    float dot = 0.f;
    #pragma unroll
    for (int i = 0; i < 8; i++) {
        float4 a = hs[i];
        float4 b = hd[i];
        dot += a.x * b.x + a.y * b.y + a.z * b.z + a.w * b.w;
    }
    float beta = __ldg(&betas[layer]);
    float v = __expf(beta * rinv[s] * rinv[d] * dot);
    ex[e] = v;
    atomicAdd(&denom[d], v);
}

// ---------------------------------------------------------------------------
// Edge pass 2: agg[d] += (ex[e]/max(denom[d],eps)) * h[s]   via vectorized RED
__global__ __launch_bounds__(256) void k_scatter(
    const int* __restrict__ src, const int* __restrict__ dst,
    const float* __restrict__ h, const float* __restrict__ ex,
    const float* __restrict__ denom, float* __restrict__ agg, int ne)
{
    int e = blockIdx.x * 256 + threadIdx.x;
    if (e >= ne) return;
    int s = src[e];
    int d = dst[e];

    float a = ex[e] / fmaxf(denom[d], EPSF);
    const float4* hs = reinterpret_cast<const float4*>(h + (size_t)s * 32);
    float4* o = reinterpret_cast<float4*>(agg + (size_t)d * 32);
    #pragma unroll
    for (int i = 0; i < 8; i++) {
        float4 hv = hs[i];
        float4 val = make_float4(a * hv.x, a * hv.y, a * hv.z, a * hv.w);
        atomicAdd(&o[i], val);   // sm_90+: RED.E.ADD.F32 vec4
    }
}

// ---------------------------------------------------------------------------
// Relu in place + row inverse-norm (for next layer's normalized dot).
__global__ __launch_bounds__(256) void k_relu_norm(
    float* __restrict__ h, float* __restrict__ rinv, int n)
{
    int node = blockIdx.x * 256 + threadIdx.x;
    if (node >= n) return;
    float4* h4 = reinterpret_cast<float4*>(h + (size_t)node * 32);
    float ss = 0.f;
    #pragma unroll
    for (int i = 0; i < 8; i++) {
        float4 v = h4[i];
        v.x = fmaxf(v.x, 0.f); v.y = fmaxf(v.y, 0.f);
        v.z = fmaxf(v.z, 0.f); v.w = fmaxf(v.w, 0.f);
        ss += v.x * v.x + v.y * v.y + v.z * v.z + v.w * v.w;
        h4[i] = v;
    }
    rinv[node] = 1.0f / fmaxf(sqrtf(ss), EPSF);
}

// ---------------------------------------------------------------------------
// Head: out = log_softmax(relu(hin) @ w2^T + b2). Thread-per-node.
__global__ __launch_bounds__(128) void k_final(
    const float* __restrict__ hin, const float* __restrict__ w2,
    const float* __restrict__ b2, float* __restrict__ out, int n)
{
    __shared__ float w2t[32 * 64];   // [k][j]
    __shared__ float b2s[64];
    for (int i = threadIdx.x; i < 2048; i += 128) {
        int j = i >> 5, k = i & 31;
        w2t[k * 64 + j] = w2[i];
    }
    for (int i = threadIdx.x; i < 64; i += 128) b2s[i] = b2[i];
    __syncthreads();

    int node = blockIdx.x * 128 + threadIdx.x;
    if (node >= n) return;

    float acc[64];
    #pragma unroll
    for (int j = 0; j < 64; j++) acc[j] = b2s[j];

    const float4* h4 = reinterpret_cast<const float4*>(hin + (size_t)node * 32);
    #pragma unroll
    for (int k4 = 0; k4 < 8; k4++) {
        float4 hv = h4[k4];
        float hh[4] = {fmaxf(hv.x, 0.f), fmaxf(hv.y, 0.f),
                       fmaxf(hv.z, 0.f), fmaxf(hv.w, 0.f)};
        #pragma unroll
        for (int c = 0; c < 4; c++) {
            const float4* w4 = reinterpret_cast<const float4*>(&w2t[(k4 * 4 + c) * 64]);
            float f = hh[c];
            #pragma unroll
            for (int j4 = 0; j4 < 16; j4++) {
                float4 w = w4[j4];
                acc[j4 * 4 + 0] += f * w.x;
                acc[j4 * 4 + 1] += f * w.y;
                acc[j4 * 4 + 2] += f * w.z;
                acc[j4 * 4 + 3] += f * w.w;
            }
        }
    }

    float mx = acc[0];
    #pragma unroll
    for (int j = 1; j < 64; j++) mx = fmaxf(mx, acc[j]);
    float sum = 0.f;
    #pragma unroll
    for (int j = 0; j < 64; j++) sum += __expf(acc[j] - mx);
    float lse = mx + __logf(sum);

    float4* o4 = reinterpret_cast<float4*>(out + (size_t)node * 64);
    #pragma unroll
    for (int j4 = 0; j4 < 16; j4++)
        o4[j4] = make_float4(acc[j4 * 4] - lse, acc[j4 * 4 + 1] - lse,
                             acc[j4 * 4 + 2] - lse, acc[j4 * 4 + 3] - lse);
}

// ---------------------------------------------------------------------------
extern "C" void kernel_launch(void* const* d_in, const int* in_sizes, int n_in,
                              void* d_out, int out_size)
{
    const float* feat  = (const float*)d_in[0];
    const int*   src   = (const int*)d_in[1];
    const int*   dst   = (const int*)d_in[2];
    const float* w1    = (const float*)d_in[3];
    const float* b1    = (const float*)d_in[4];
    const float* betas = (const float*)d_in[5];
    const float* w2    = (const float*)d_in[6];
    const float* b2    = (const float*)d_in[7];
    float*       out   = (float*)d_out;

    const int n  = in_sizes[0] / 128;   // 100000
    const int ne = in_sizes[1];         // 1600000

    float *bufA, *bufB, *rinv, *ex, *denom;
    cudaGetSymbolAddress((void**)&bufA,  g_bufA);
    cudaGetSymbolAddress((void**)&bufB,  g_bufB);
    cudaGetSymbolAddress((void**)&rinv,  g_rinv);
    cudaGetSymbolAddress((void**)&ex,    g_ex);
    cudaGetSymbolAddress((void**)&denom, g_denom);

    const int TB = 256;
    const int n_agg4 = n * 32 / 4;
    const int n_den4 = n / 4;
    dim3 gN((n + TB - 1) / TB);
    dim3 gE((ne + TB - 1) / TB);
    dim3 gZ((n_agg4 + TB - 1) / TB);

    // K1: h1 = relu(F @ w1^T + b1) -> bufA, rinv
    k_gemm1<<<gN, TB>>>(feat, w1, b1, bufA, rinv, n);

    // ---- layer 0: bufA -> bufB ----
    k_zero_layer<<<gZ, TB>>>((float4*)bufB, (float4*)denom, n_agg4, n_den4);
    k_edge<<<gE, TB>>>(src, dst, bufA, rinv, betas, 0, ex, denom, ne);
    k_scatter<<<gE, TB>>>(src, dst, bufA, ex, denom, bufB, ne);
    k_relu_norm<<<gN, TB>>>(bufB, rinv, n);

    // ---- layer 1: bufB -> bufA ----
    k_zero_layer<<<gZ, TB>>>((float4*)bufA, (float4*)denom, n_agg4, n_den4);
    k_edge<<<gE, TB>>>(src, dst, bufB, rinv, betas, 1, ex, denom, ne);
    k_scatter<<<gE, TB>>>(src, dst, bufB, ex, denom, bufA, ne);

    // K5: head (relu fused) -> out
    k_final<<<(n + 127) / 128, 128>>>(bufA, w2, b2, out, n);
}

// round 4
// speedup vs baseline: 2.1440x; 2.1440x over previous
#include <cuda_runtime.h>
#include <math.h>

// ---------------------------------------------------------------------------
// AGNN: features[100000,128] f32, src/dst[1.6M] int32, w1[32,128], b1[32],
//       betas[2], w2[64,32], b2[64]  ->  out[100000,64] f32 (log_softmax)
//
// Pipeline (edge passes FUSED; softmax denom divided at node level):
//   K1  gemm1+relu+rownorm : h1 = relu(F @ w1^T + b1), rinv = 1/max(||h1||,eps)
//   per layer L in {0,1}:
//     zero(agg + denom)
//     K2  edge_fused (8 lanes/edge):
//           dot = <h[s],h[d]>;  v = exp(beta*rinv[s]*rinv[d]*dot)
//           denom[d] += v;  agg[d] += v*h[s]        (coalesced vec4 RED)
//     K3  norm: h = agg/max(denom,eps)  [+relu+rinv after layer0]
//   K5  head: out = log_softmax(relu(h2) @ w2^T + b2)
// Max-subtraction in edge softmax skipped: e = beta*cosine, |e| <= |beta|,
// so exp(e) is bounded — identical result.
// ---------------------------------------------------------------------------

#define NN 100000
#define NE 1600000
#define EPSF 1e-12f

__device__ __align__(128) float g_bufA[NN * 32];
__device__ __align__(128) float g_bufB[NN * 32];
__device__ __align__(128) float g_rinv[NN];
__device__ __align__(128) float g_denom[NN];

// ---------------------------------------------------------------------------
// Zero agg (n*32 floats) and denom (n floats) in one kernel.
__global__ void k_zero_layer(float4* __restrict__ agg, float4* __restrict__ denom,
                             int n_agg4, int n_den4) {
    int i = blockIdx.x * blockDim.x + threadIdx.x;
    if (i < n_agg4) agg[i] = make_float4(0.f, 0.f, 0.f, 0.f);
    if (i < n_den4) denom[i] = make_float4(0.f, 0.f, 0.f, 0.f);
}

// ---------------------------------------------------------------------------
// GEMM1: thread-per-node, w1 transposed into smem, 32 accumulators.
__global__ __launch_bounds__(256) void k_gemm1(
    const float* __restrict__ feat, const float* __restrict__ w1,
    const float* __restrict__ b1, float* __restrict__ h,
    float* __restrict__ rinv, int n)
{
    __shared__ float w1t[128 * 32];   // [k][j]
    __shared__ float b1s[32];
    for (int i = threadIdx.x; i < 4096; i += 256) {
        int j = i >> 7, k = i & 127;
        w1t[k * 32 + j] = w1[i];
    }
    if (threadIdx.x < 32) b1s[threadIdx.x] = b1[threadIdx.x];
    __syncthreads();

    int node = blockIdx.x * 256 + threadIdx.x;
    if (node >= n) return;

    float acc[32];
    #pragma unroll
    for (int j = 0; j < 32; j++) acc[j] = b1s[j];

    const float4* f4 = reinterpret_cast<const float4*>(feat + (size_t)node * 128);
    #pragma unroll 4
    for (int k4 = 0; k4 < 32; k4++) {
        float4 f = f4[k4];
        float fv[4] = {f.x, f.y, f.z, f.w};
        #pragma unroll
        for (int c = 0; c < 4; c++) {
            const float4* w4 = reinterpret_cast<const float4*>(&w1t[(k4 * 4 + c) * 32]);
            #pragma unroll
            for (int j4 = 0; j4 < 8; j4++) {
                float4 w = w4[j4];
                acc[j4 * 4 + 0] += fv[c] * w.x;
                acc[j4 * 4 + 1] += fv[c] * w.y;
                acc[j4 * 4 + 2] += fv[c] * w.z;
                acc[j4 * 4 + 3] += fv[c] * w.w;
            }
        }
    }

    float ss = 0.f;
    #pragma unroll
    for (int j = 0; j < 32; j++) {
        float v = fmaxf(acc[j], 0.f);
        acc[j] = v;
        ss += v * v;
    }
    rinv[node] = 1.0f / fmaxf(sqrtf(ss), EPSF);

    float4* o4 = reinterpret_cast<float4*>(h + (size_t)node * 32);
    #pragma unroll
    for (int j4 = 0; j4 < 8; j4++)
        o4[j4] = make_float4(acc[j4 * 4], acc[j4 * 4 + 1], acc[j4 * 4 + 2], acc[j4 * 4 + 3]);
}

// ---------------------------------------------------------------------------
// Fused edge pass, 8 lanes per edge (lane l owns float4 #l of the 32-f row).
//   v = exp(beta * rinv[s]*rinv[d] * dot(h[s],h[d]))
//   denom[d] += v (lane 0);  agg[d] += v * h[s] (all lanes, coalesced RED.128)
__global__ __launch_bounds__(256) void k_edge_fused(
    const int* __restrict__ src, const int* __restrict__ dst,
    const float* __restrict__ h, const float* __restrict__ rinv,
    const float* __restrict__ betas, int layer,
    float* __restrict__ denom, float* __restrict__ agg, int ne)
{
    int gid  = blockIdx.x * 256 + threadIdx.x;
    int e    = gid >> 3;
    int lane = threadIdx.x & 7;
    if (e >= ne) return;
    unsigned mask = __activemask();   // groups are uniformly active

    int s = src[e];
    int d = dst[e];

    const float4 a = *reinterpret_cast<const float4*>(h + (size_t)s * 32 + lane * 4);
    const float4 b = *reinterpret_cast<const float4*>(h + (size_t)d * 32 + lane * 4);

    float p = a.x * b.x + a.y * b.y + a.z * b.z + a.w * b.w;
    p += __shfl_xor_sync(mask, p, 1);
    p += __shfl_xor_sync(mask, p, 2);
    p += __shfl_xor_sync(mask, p, 4);   // all 8 lanes hold full dot

    float v = __expf(__ldg(&betas[layer]) * rinv[s] * rinv[d] * p);

    if (lane == 0) atomicAdd(&denom[d], v);
    float4* o = reinterpret_cast<float4*>(agg + (size_t)d * 32 + lane * 4);
    atomicAdd(o, make_float4(v * a.x, v * a.y, v * a.z, v * a.w));
}

// ---------------------------------------------------------------------------
// Node pass: h = agg / max(denom,eps); optional relu; optional rinv for next layer.
__global__ __launch_bounds__(256) void k_norm(
    float* __restrict__ h, const float* __restrict__ denom,
    float* __restrict__ rinv, int n, int do_relu_rinv)
{
    int node = blockIdx.x * 256 + threadIdx.x;
    if (node >= n) return;
    float inv = 1.0f / fmaxf(denom[node], EPSF);
    float4* h4 = reinterpret_cast<float4*>(h + (size_t)node * 32);
    float ss = 0.f;
    #pragma unroll
    for (int i = 0; i < 8; i++) {
        float4 v = h4[i];
        v.x *= inv; v.y *= inv; v.z *= inv; v.w *= inv;
        if (do_relu_rinv) {
            v.x = fmaxf(v.x, 0.f); v.y = fmaxf(v.y, 0.f);
            v.z = fmaxf(v.z, 0.f); v.w = fmaxf(v.w, 0.f);
            ss += v.x * v.x + v.y * v.y + v.z * v.z + v.w * v.w;
        }
        h4[i] = v;
    }
    if (do_relu_rinv)
        rinv[node] = 1.0f / fmaxf(sqrtf(ss), EPSF);
}

// ---------------------------------------------------------------------------
// Head: out = log_softmax(relu(hin) @ w2^T + b2). Thread-per-node.
__global__ __launch_bounds__(128) void k_final(
    const float* __restrict__ hin, const float* __restrict__ w2,
    const float* __restrict__ b2, float* __restrict__ out, int n)
{
    __shared__ float w2t[32 * 64];   // [k][j]
    __shared__ float b2s[64];
    for (int i = threadIdx.x; i < 2048; i += 128) {
        int j = i >> 5, k = i & 31;
        w2t[k * 64 + j] = w2[i];
    }
    for (int i = threadIdx.x; i < 64; i += 128) b2s[i] = b2[i];
    __syncthreads();

    int node = blockIdx.x * 128 + threadIdx.x;
    if (node >= n) return;

    float acc[64];
    #pragma unroll
    for (int j = 0; j < 64; j++) acc[j] = b2s[j];

    const float4* h4 = reinterpret_cast<const float4*>(hin + (size_t)node * 32);
    #pragma unroll
    for (int k4 = 0; k4 < 8; k4++) {
        float4 hv = h4[k4];
        float hh[4] = {fmaxf(hv.x, 0.f), fmaxf(hv.y, 0.f),
                       fmaxf(hv.z, 0.f), fmaxf(hv.w, 0.f)};
        #pragma unroll
        for (int c = 0; c < 4; c++) {
            const float4* w4 = reinterpret_cast<const float4*>(&w2t[(k4 * 4 + c) * 64]);
            float f = hh[c];
            #pragma unroll
            for (int j4 = 0; j4 < 16; j4++) {
                float4 w = w4[j4];
                acc[j4 * 4 + 0] += f * w.x;
                acc[j4 * 4 + 1] += f * w.y;
                acc[j4 * 4 + 2] += f * w.z;
                acc[j4 * 4 + 3] += f * w.w;
            }
        }
    }

    float mx = acc[0];
    #pragma unroll
    for (int j = 1; j < 64; j++) mx = fmaxf(mx, acc[j]);
    float sum = 0.f;
    #pragma unroll
    for (int j = 0; j < 64; j++) sum += __expf(acc[j] - mx);
    float lse = mx + __logf(sum);

    float4* o4 = reinterpret_cast<float4*>(out + (size_t)node * 64);
    #pragma unroll
    for (int j4 = 0; j4 < 16; j4++)
        o4[j4] = make_float4(acc[j4 * 4] - lse, acc[j4 * 4 + 1] - lse,
                             acc[j4 * 4 + 2] - lse, acc[j4 * 4 + 3] - lse);
}

// ---------------------------------------------------------------------------
extern "C" void kernel_launch(void* const* d_in, const int* in_sizes, int n_in,
                              void* d_out, int out_size)
{
    const float* feat  = (const float*)d_in[0];
    const int*   src   = (const int*)d_in[1];
    const int*   dst   = (const int*)d_in[2];
    const float* w1    = (const float*)d_in[3];
    const float* b1    = (const float*)d_in[4];
    const float* betas = (const float*)d_in[5];
    const float* w2    = (const float*)d_in[6];
    const float* b2    = (const float*)d_in[7];
    float*       out   = (float*)d_out;

    const int n  = in_sizes[0] / 128;   // 100000
    const int ne = in_sizes[1];         // 1600000

    float *bufA, *bufB, *rinv, *denom;
    cudaGetSymbolAddress((void**)&bufA,  g_bufA);
    cudaGetSymbolAddress((void**)&bufB,  g_bufB);
    cudaGetSymbolAddress((void**)&rinv,  g_rinv);
    cudaGetSymbolAddress((void**)&denom, g_denom);

    const int TB = 256;
    const int n_agg4 = n * 32 / 4;
    const int n_den4 = n / 4;
    dim3 gN((n + TB - 1) / TB);
    dim3 gE8(((size_t)ne * 8 + TB - 1) / TB);
    dim3 gZ((n_agg4 + TB - 1) / TB);

    // K1: h1 = relu(F @ w1^T + b1) -> bufA, rinv
    k_gemm1<<<gN, TB>>>(feat, w1, b1, bufA, rinv, n);

    // ---- layer 0: bufA -> bufB ----
    k_zero_layer<<<gZ, TB>>>((float4*)bufB, (float4*)denom, n_agg4, n_den4);
    k_edge_fused<<<gE8, TB>>>(src, dst, bufA, rinv, betas, 0, denom, bufB, ne);
    k_norm<<<gN, TB>>>(bufB, denom, rinv, n, 1);

    // ---- layer 1: bufB -> bufA ----
    k_zero_layer<<<gZ, TB>>>((float4*)bufA, (float4*)denom, n_agg4, n_den4);
    k_edge_fused<<<gE8, TB>>>(src, dst, bufB, rinv, betas, 1, denom, bufA, ne);
    k_norm<<<gN, TB>>>(bufA, denom, rinv, n, 0);

    // K5: head (relu fused) -> out
    k_final<<<(n + 127) / 128, 128>>>(bufA, w2, b2, out, n);
}

// round 5
// speedup vs baseline: 2.4141x; 1.1260x over previous
#include <cuda_runtime.h>
#include <cuda_fp16.h>
#include <math.h>

// ---------------------------------------------------------------------------
// AGNN — fp16 normalized-feature edge passes.
//   hn[node] = h/||h|| in fp16 (64 B/row), norm[node] = max(||h||,eps).
//   edge: e = beta * dot(hn_s, hn_d)  (cosine directly, no rinv loads)
//         v = exp(e);  denom[d] += v;  agg[d] += (v*norm[s]) * hn[s]  (f32 RED)
//   node: h_next = relu(agg/denom)  -> re-normalize into hn/norm (layer0)
//   final: out = log_softmax(relu(agg/denom) @ w2^T + b2)   (layer1 norm fused)
// Max-subtraction skipped: |e| <= |beta| (cosine bounded) — exact same math.
// ---------------------------------------------------------------------------

#define NN 100000
#define NE 1600000
#define EPSF 1e-12f

__device__ __align__(128) float  g_agg[NN * 32];     // scatter accumulator (f32)
__device__ __align__(128) __half g_hnA[NN * 32];     // normalized features fp16
__device__ __align__(128) __half g_hnB[NN * 32];
__device__ __align__(128) float  g_norm[NN];
__device__ __align__(128) float  g_denom[NN];

// ---------------------------------------------------------------------------
__global__ void k_zero_layer(float4* __restrict__ agg, float4* __restrict__ denom,
                             int n_agg4, int n_den4) {
    int i = blockIdx.x * blockDim.x + threadIdx.x;
    if (i < n_agg4) agg[i] = make_float4(0.f, 0.f, 0.f, 0.f);
    if (i < n_den4) denom[i] = make_float4(0.f, 0.f, 0.f, 0.f);
}

// ---------------------------------------------------------------------------
// GEMM1: h1 = relu(F @ w1^T + b1); write hn (fp16 normalized) + norm.
__global__ __launch_bounds__(256) void k_gemm1(
    const float* __restrict__ feat, const float* __restrict__ w1,
    const float* __restrict__ b1, __half* __restrict__ hn,
    float* __restrict__ normv, int n)
{
    __shared__ float w1t[128 * 32];   // [k][j]
    __shared__ float b1s[32];
    for (int i = threadIdx.x; i < 4096; i += 256) {
        int j = i >> 7, k = i & 127;
        w1t[k * 32 + j] = w1[i];
    }
    if (threadIdx.x < 32) b1s[threadIdx.x] = b1[threadIdx.x];
    __syncthreads();

    int node = blockIdx.x * 256 + threadIdx.x;
    if (node >= n) return;

    float acc[32];
    #pragma unroll
    for (int j = 0; j < 32; j++) acc[j] = b1s[j];

    const float4* f4 = reinterpret_cast<const float4*>(feat + (size_t)node * 128);
    #pragma unroll 4
    for (int k4 = 0; k4 < 32; k4++) {
        float4 f = f4[k4];
        float fv[4] = {f.x, f.y, f.z, f.w};
        #pragma unroll
        for (int c = 0; c < 4; c++) {
            const float4* w4 = reinterpret_cast<const float4*>(&w1t[(k4 * 4 + c) * 32]);
            #pragma unroll
            for (int j4 = 0; j4 < 8; j4++) {
                float4 w = w4[j4];
                acc[j4 * 4 + 0] += fv[c] * w.x;
                acc[j4 * 4 + 1] += fv[c] * w.y;
                acc[j4 * 4 + 2] += fv[c] * w.z;
                acc[j4 * 4 + 3] += fv[c] * w.w;
            }
        }
    }

    float ss = 0.f;
    #pragma unroll
    for (int j = 0; j < 32; j++) {
        float v = fmaxf(acc[j], 0.f);
        acc[j] = v;
        ss += v * v;
    }
    float nv = fmaxf(sqrtf(ss), EPSF);
    float rinv = 1.0f / nv;
    normv[node] = nv;

    __half2 hp[16];
    #pragma unroll
    for (int j = 0; j < 16; j++)
        hp[j] = __floats2half2_rn(acc[2 * j] * rinv, acc[2 * j + 1] * rinv);
    uint4* o = reinterpret_cast<uint4*>(hn + (size_t)node * 32);
    const uint4* src4 = reinterpret_cast<const uint4*>(hp);
    #pragma unroll
    for (int j = 0; j < 4; j++) o[j] = src4[j];
}

// ---------------------------------------------------------------------------
// Fused edge pass, 8 lanes/edge. hn fp16 gathers (64 B/row), f32 vec4 RED.
__global__ __launch_bounds__(256) void k_edge_fused(
    const int* __restrict__ src, const int* __restrict__ dst,
    const __half* __restrict__ hn, const float* __restrict__ normv,
    const float* __restrict__ betas, int layer,
    float* __restrict__ denom, float* __restrict__ agg, int ne)
{
    int gid  = blockIdx.x * 256 + threadIdx.x;
    int e    = gid >> 3;
    int lane = threadIdx.x & 7;
    if (e >= ne) return;
    unsigned mask = __activemask();

    int s = src[e];
    int d = dst[e];

    const uint2 pa = *(reinterpret_cast<const uint2*>(hn + (size_t)s * 32) + lane);
    const uint2 pb = *(reinterpret_cast<const uint2*>(hn + (size_t)d * 32) + lane);

    float2 a0 = __half22float2(*reinterpret_cast<const __half2*>(&pa.x));
    float2 a1 = __half22float2(*reinterpret_cast<const __half2*>(&pa.y));
    float2 b0 = __half22float2(*reinterpret_cast<const __half2*>(&pb.x));
    float2 b1 = __half22float2(*reinterpret_cast<const __half2*>(&pb.y));

    float p = a0.x * b0.x + a0.y * b0.y + a1.x * b1.x + a1.y * b1.y;
    p += __shfl_xor_sync(mask, p, 1);
    p += __shfl_xor_sync(mask, p, 2);
    p += __shfl_xor_sync(mask, p, 4);   // all 8 lanes: full cosine dot

    float v = __expf(__ldg(&betas[layer]) * p);
    float w = v * __ldg(&normv[s]);

    if (lane == 0) atomicAdd(&denom[d], v);
    float4* o = reinterpret_cast<float4*>(agg + (size_t)d * 32) + lane;
    atomicAdd(o, make_float4(w * a0.x, w * a0.y, w * a1.x, w * a1.y));
}

// ---------------------------------------------------------------------------
// Layer-0 node pass, 8 lanes/node: h = relu(agg/denom); write hn fp16 + norm.
__global__ __launch_bounds__(256) void k_norm_mid(
    const float* __restrict__ agg, const float* __restrict__ denom,
    __half* __restrict__ hn, float* __restrict__ normv, int n)
{
    int gid  = blockIdx.x * 256 + threadIdx.x;
    int node = gid >> 3;
    int lane = threadIdx.x & 7;
    if (node >= n) return;
    unsigned mask = __activemask();

    float inv = 1.0f / fmaxf(denom[node], EPSF);
    float4 v = *(reinterpret_cast<const float4*>(agg + (size_t)node * 32) + lane);
    v.x = fmaxf(v.x * inv, 0.f); v.y = fmaxf(v.y * inv, 0.f);
    v.z = fmaxf(v.z * inv, 0.f); v.w = fmaxf(v.w * inv, 0.f);

    float ss = v.x * v.x + v.y * v.y + v.z * v.z + v.w * v.w;
    ss += __shfl_xor_sync(mask, ss, 1);
    ss += __shfl_xor_sync(mask, ss, 2);
    ss += __shfl_xor_sync(mask, ss, 4);

    float nv = fmaxf(sqrtf(ss), EPSF);
    float rinv = 1.0f / nv;
    if (lane == 0) normv[node] = nv;

    __half2 h0 = __floats2half2_rn(v.x * rinv, v.y * rinv);
    __half2 h1 = __floats2half2_rn(v.z * rinv, v.w * rinv);
    uint2 pk;
    pk.x = *reinterpret_cast<unsigned*>(&h0);
    pk.y = *reinterpret_cast<unsigned*>(&h1);
    *(reinterpret_cast<uint2*>(hn + (size_t)node * 32) + lane) = pk;
}

// ---------------------------------------------------------------------------
// Head: h2 = relu(agg/denom); out = log_softmax(h2 @ w2^T + b2).
__global__ __launch_bounds__(128) void k_final(
    const float* __restrict__ agg, const float* __restrict__ denom,
    const float* __restrict__ w2, const float* __restrict__ b2,
    float* __restrict__ out, int n)
{
    __shared__ float w2t[32 * 64];   // [k][j]
    __shared__ float b2s[64];
    for (int i = threadIdx.x; i < 2048; i += 128) {
        int j = i >> 5, k = i & 31;
        w2t[k * 64 + j] = w2[i];
    }
    for (int i = threadIdx.x; i < 64; i += 128) b2s[i] = b2[i];
    __syncthreads();

    int node = blockIdx.x * 128 + threadIdx.x;
    if (node >= n) return;

    float inv = 1.0f / fmaxf(denom[node], EPSF);

    float acc[64];
    #pragma unroll
    for (int j = 0; j < 64; j++) acc[j] = b2s[j];

    const float4* h4 = reinterpret_cast<const float4*>(agg + (size_t)node * 32);
    #pragma unroll
    for (int k4 = 0; k4 < 8; k4++) {
        float4 hv = h4[k4];
        float hh[4] = {fmaxf(hv.x * inv, 0.f), fmaxf(hv.y * inv, 0.f),
                       fmaxf(hv.z * inv, 0.f), fmaxf(hv.w * inv, 0.f)};
        #pragma unroll
        for (int c = 0; c < 4; c++) {
            const float4* w4 = reinterpret_cast<const float4*>(&w2t[(k4 * 4 + c) * 64]);
            float f = hh[c];
            #pragma unroll
            for (int j4 = 0; j4 < 16; j4++) {
                float4 w = w4[j4];
                acc[j4 * 4 + 0] += f * w.x;
                acc[j4 * 4 + 1] += f * w.y;
                acc[j4 * 4 + 2] += f * w.z;
                acc[j4 * 4 + 3] += f * w.w;
            }
        }
    }

    float mx = acc[0];
    #pragma unroll
    for (int j = 1; j < 64; j++) mx = fmaxf(mx, acc[j]);
    float sum = 0.f;
    #pragma unroll
    for (int j = 0; j < 64; j++) sum += __expf(acc[j] - mx);
    float lse = mx + __logf(sum);

    float4* o4 = reinterpret_cast<float4*>(out + (size_t)node * 64);
    #pragma unroll
    for (int j4 = 0; j4 < 16; j4++)
        o4[j4] = make_float4(acc[j4 * 4] - lse, acc[j4 * 4 + 1] - lse,
                             acc[j4 * 4 + 2] - lse, acc[j4 * 4 + 3] - lse);
}

// ---------------------------------------------------------------------------
extern "C" void kernel_launch(void* const* d_in, const int* in_sizes, int n_in,
                              void* d_out, int out_size)
{
    const float* feat  = (const float*)d_in[0];
    const int*   src   = (const int*)d_in[1];
    const int*   dst   = (const int*)d_in[2];
    const float* w1    = (const float*)d_in[3];
    const float* b1    = (const float*)d_in[4];
    const float* betas = (const float*)d_in[5];
    const float* w2    = (const float*)d_in[6];
    const float* b2    = (const float*)d_in[7];
    float*       out   = (float*)d_out;

    const int n  = in_sizes[0] / 128;   // 100000
    const int ne = in_sizes[1];         // 1600000

    float *agg, *normv, *denom;
    __half *hnA, *hnB;
    cudaGetSymbolAddress((void**)&agg,   g_agg);
    cudaGetSymbolAddress((void**)&hnA,   g_hnA);
    cudaGetSymbolAddress((void**)&hnB,   g_hnB);
    cudaGetSymbolAddress((void**)&normv, g_norm);
    cudaGetSymbolAddress((void**)&denom, g_denom);

    const int TB = 256;
    const int n_agg4 = n * 32 / 4;
    const int n_den4 = n / 4;
    dim3 gN((n + TB - 1) / TB);
    dim3 gN8(((size_t)n * 8 + TB - 1) / TB);
    dim3 gE8(((size_t)ne * 8 + TB - 1) / TB);
    dim3 gZ((n_agg4 + TB - 1) / TB);

    // K1: hn0 = normalize(relu(F @ w1^T + b1)), norm0
    k_gemm1<<<gN, TB>>>(feat, w1, b1, hnA, normv, n);

    // ---- layer 0 ----
    k_zero_layer<<<gZ, TB>>>((float4*)agg, (float4*)denom, n_agg4, n_den4);
    k_edge_fused<<<gE8, TB>>>(src, dst, hnA, normv, betas, 0, denom, agg, ne);
    k_norm_mid<<<gN8, TB>>>(agg, denom, hnB, normv, n);

    // ---- layer 1 ----
    k_zero_layer<<<gZ, TB>>>((float4*)agg, (float4*)denom, n_agg4, n_den4);
    k_edge_fused<<<gE8, TB>>>(src, dst, hnB, normv, betas, 1, denom, agg, ne);

    // K5: head (relu + denom divide fused) -> out
    k_final<<<(n + 127) / 128, 128>>>(agg, denom, w2, b2, out, n);
}